// round 3
// baseline (speedup 1.0000x reference)
#include <cuda_runtime.h>
#include <cstdint>

typedef unsigned long long u64;

#define NB 8
#define NT 1024
#define NS 64
#define DM 256
#define DH 128

// scratch: s_proj[b][n][h]  (8*64*128 floats = 256KB)
__device__ float g_sproj[NB * NS * DH];

// ---------------- packed f32x2 helpers ----------------
__device__ __forceinline__ u64 pk_fma(u64 acc, u64 a, u64 b) {
    asm("fma.rn.f32x2 %0, %1, %2, %0;" : "+l"(acc) : "l"(a), "l"(b));
    return acc;
}

// acc += relu(f2 + s2) * w2   (packed pair; relu via scalar max on halves)
__device__ __forceinline__ u64 relu_fma2(u64 acc, u64 f2, u64 s2, u64 w2) {
    asm("{\n\t"
        ".reg .b64 t;\n\t"
        ".reg .f32 lo, hi;\n\t"
        "add.rn.f32x2 t, %1, %2;\n\t"
        "mov.b64 {lo, hi}, t;\n\t"
        "max.f32 lo, lo, 0f00000000;\n\t"
        "max.f32 hi, hi, 0f00000000;\n\t"
        "mov.b64 t, {lo, hi};\n\t"
        "fma.rn.f32x2 %0, t, %3, %0;\n\t"
        "}"
        : "+l"(acc) : "l"(f2), "l"(s2), "l"(w2));
    return acc;
}

__device__ __forceinline__ float pk_sum(u64 a) {
    return __uint_as_float((unsigned)a) + __uint_as_float((unsigned)(a >> 32));
}

// ---------------- kernel 1: s_proj = slots @ W_s + b_proj ----------------
__global__ void __launch_bounds__(128) sproj_kernel(
    const float* __restrict__ slots, const float* __restrict__ W_proj,
    const float* __restrict__ b_proj)
{
    __shared__ float srow[DM];
    const int row = blockIdx.x;          // b*64 + n   (512 rows)
    const int h = threadIdx.x;           // 0..127
    const float* s = slots + row * DM;
    srow[h] = s[h];
    srow[h + 128] = s[h + 128];
    __syncthreads();
    const float* W = W_proj + DM * DH;   // W_s block
    float acc = b_proj[h];
#pragma unroll 8
    for (int k = 0; k < DM; k++) {
        acc = fmaf(srow[k], __ldg(&W[k * DH + h]), acc);
    }
    g_sproj[row * DH + h] = acc;
}

// ---------------- kernel 2: fused f_proj GEMM + relu-head ----------------
// smem layout (floats):
#define PF 130                       // f/s tile pitch
#define PA 68                        // A tile pitch
#define AS_OFF 8320                  // after f tile (64*130)
#define BS_OFF 12672                 // after A tile (64*68)
#define SS_OFF 8320                  // phase2: s tile reuses A/B region
#define WS_OFF 16640                 // w_head (128 floats)
#define SMEM_FLOATS 20864            // = BS_OFF + 128*64
#define SMEM_BYTES (SMEM_FLOATS * 4) // 83456 B

__global__ void __launch_bounds__(256) main_kernel(
    const float* __restrict__ features, const float* __restrict__ W_proj,
    const float* __restrict__ w_head, const float* __restrict__ b_head,
    float* __restrict__ out)
{
    extern __shared__ float sm[];
    const int tid = threadIdx.x;
    const int b  = blockIdx.x >> 4;          // 0..7
    const int t0 = (blockIdx.x & 15) << 6;   // 0,64,...,960
    const int mq = tid >> 4;                 // 0..15
    const int nq = tid & 15;                 // 0..15

    float* fS = sm;
    float* aS = sm + AS_OFF;
    float* bS = sm + BS_OFF;

    // ======== Phase 1: f[64][128] = features[b, t0:t0+64, :] @ W_f ========
    u64 acc1[4][8];
#pragma unroll
    for (int i = 0; i < 4; i++)
#pragma unroll
        for (int j = 0; j < 8; j++) acc1[i][j] = 0ull;

    for (int kc = 0; kc < 4; kc++) {
        const int k0 = kc << 6;
        __syncthreads();
        // stage A: 64 rows x 64 k  (coalesced; warp = one 32-float run of a row)
#pragma unroll
        for (int q = 0; q < 16; q++) {
            int fid = tid + (q << 8);
            int m = fid >> 6, k = fid & 63;
            aS[m * PA + k] = features[((size_t)(b * NT + t0 + m)) * DM + k0 + k];
        }
        // stage B transposed + pair-swizzled: element (k,h) -> bS[h*64 + 2*((k>>1)^(h&15)) + (k&1)]
#pragma unroll
        for (int q = 0; q < 32; q++) {
            int fid = tid + (q << 8);
            int h = fid & 127, k = fid >> 7;
            int kk = 2 * ((k >> 1) ^ (h & 15)) + (k & 1);
            bS[(h << 6) + kk] = W_proj[(k0 + k) * DH + h];
        }
        __syncthreads();
#pragma unroll 8
        for (int k2 = 0; k2 < 32; k2++) {
            u64 a2[4], b2[8];
#pragma unroll
            for (int i = 0; i < 4; i++)
                a2[i] = *(const u64*)&aS[(mq + 16 * i) * PA + 2 * k2];
            const int swz = 2 * (k2 ^ nq);   // (n & 15) == nq for all j
#pragma unroll
            for (int j = 0; j < 8; j++)
                b2[j] = *(const u64*)&bS[((nq + 16 * j) << 6) + swz];
#pragma unroll
            for (int i = 0; i < 4; i++)
#pragma unroll
                for (int j = 0; j < 8; j++)
                    acc1[i][j] = pk_fma(acc1[i][j], a2[i], b2[j]);
        }
    }
    // write f tile to smem (scalar: lo(even-k) + hi(odd-k))
#pragma unroll
    for (int i = 0; i < 4; i++)
#pragma unroll
        for (int j = 0; j < 8; j++)
            fS[(mq + 16 * i) * PF + (nq + 16 * j)] = pk_sum(acc1[i][j]);

    __syncthreads();   // all phase-1 smem reads + f stores done before region reuse

    // ======== Phase 2: out[t,n] = sum_h relu(f[t,h]+s[n,h])*w[h] + b ========
    float* sS = sm + SS_OFF;
    float* wS = sm + WS_OFF;
    {
        const float* gsp = g_sproj + b * (NS * DH);
#pragma unroll
        for (int q = 0; q < 32; q++) {
            int fid = tid + (q << 8);
            int n = fid >> 7, h = fid & 127;
            sS[n * PF + h] = gsp[fid];
        }
        if (tid < 128) wS[tid] = w_head[tid];
    }
    __syncthreads();

    u64 acc[4][4];
#pragma unroll
    for (int i = 0; i < 4; i++)
#pragma unroll
        for (int j = 0; j < 4; j++) acc[i][j] = 0ull;

#pragma unroll 4
    for (int h2 = 0; h2 < 64; h2++) {
        u64 w2 = *(const u64*)&wS[2 * h2];
        u64 f2[4], s2[4];
#pragma unroll
        for (int i = 0; i < 4; i++)
            f2[i] = *(const u64*)&fS[(mq + 16 * i) * PF + 2 * h2];
#pragma unroll
        for (int j = 0; j < 4; j++)
            s2[j] = *(const u64*)&sS[(nq + 16 * j) * PF + 2 * h2];
#pragma unroll
        for (int i = 0; i < 4; i++)
#pragma unroll
            for (int j = 0; j < 4; j++)
                acc[i][j] = relu_fma2(acc[i][j], f2[i], s2[j], w2);
    }

    const float bh = __ldg(b_head);
    float* ob = out + ((size_t)(b * NT + t0)) * NS;
#pragma unroll
    for (int i = 0; i < 4; i++)
#pragma unroll
        for (int j = 0; j < 4; j++)
            ob[(mq + 16 * i) * NS + (nq + 16 * j)] = pk_sum(acc[i][j]) + bh;
}

// ---------------- launch ----------------
extern "C" void kernel_launch(void* const* d_in, const int* in_sizes, int n_in,
                              void* d_out, int out_size)
{
    const float* features = (const float*)d_in[0];   // (8,1024,256)
    const float* slots    = (const float*)d_in[1];   // (8,64,256)
    const float* W_proj   = (const float*)d_in[2];   // (512,128)
    const float* b_proj   = (const float*)d_in[3];   // (128,)
    const float* w_head   = (const float*)d_in[4];   // (128,)
    const float* b_head   = (const float*)d_in[5];   // ()
    float* out = (float*)d_out;                      // (8,1024,64)

    (void)in_sizes; (void)n_in; (void)out_size;

    cudaFuncSetAttribute(main_kernel, cudaFuncAttributeMaxDynamicSharedMemorySize, SMEM_BYTES);

    sproj_kernel<<<NB * NS, 128>>>(slots, W_proj, b_proj);
    main_kernel<<<NB * (NT / 64), 256, SMEM_BYTES>>>(features, W_proj, w_head, b_head, out);
}